// round 5
// baseline (speedup 1.0000x reference)
#include <cuda_runtime.h>
#include <cuda_fp16.h>
#include <cstdint>

#define T_TOK   32768
#define IN_DIM  2048
#define OUT_DIM 768
#define NEXP    64
#define RRANK   16
#define SCALING 2.0f

#define BM 128
#define BN 128
#define BK 64
#define KT2 (IN_DIM / BK)                  /* 32 */
#define MAX_MTILES 320
#define NT 6
#define NTHREADS 256

// smem row strides (bytes), conflict-free for ldmatrix (stride/16 odd)
#define SA  144   /* A: 64 halves + pad;  9r mod 8 distinct  */
#define SB  272   /* B: 128 halves + pad; 17k mod 8 distinct */
#define SWA 48    /* WA: 16 halves + pad; 3k mod 8 distinct  */

#define SM_A0   0
#define SM_A1   18432
#define SM_B0   36864
#define SM_B1   54272
#define SM_WA0  71680
#define SM_WA1  74752
#define SM_MSZ  77824
#define SMEM_BYTES 78336   /* 2 CTAs/SM: 2*78336 < 228KB */

// fp16 scratch (converted once per launch by prepass kernels)
__device__ __align__(16) __half g_xh [(size_t)T_TOK * IN_DIM];
__device__ __align__(16) __half g_wbh[(size_t)NEXP * IN_DIM * OUT_DIM];
__device__ __align__(16) __half g_wah[(size_t)NEXP * IN_DIM * RRANK];
__device__ __align__(16) __half g_wsh[(size_t)NEXP * RRANK * OUT_DIM];

__device__ __forceinline__ uint32_t h2u(__half2 h) {
    return *reinterpret_cast<uint32_t*>(&h);
}

__device__ __forceinline__ void cp16(uint32_t dst, const void* src, bool valid) {
    int sz = valid ? 16 : 0;   // sz=0 zero-fills, reads nothing
    asm volatile("cp.async.cg.shared.global [%0], [%1], 16, %2;\n"
                 :: "r"(dst), "l"(src), "r"(sz));
}

__device__ __forceinline__ void ldsm_x4(uint32_t* r, uint32_t addr) {
    asm volatile("ldmatrix.sync.aligned.m8n8.x4.shared.b16 {%0,%1,%2,%3}, [%4];"
                 : "=r"(r[0]), "=r"(r[1]), "=r"(r[2]), "=r"(r[3]) : "r"(addr));
}
__device__ __forceinline__ void ldsm_x4_t(uint32_t* r, uint32_t addr) {
    asm volatile("ldmatrix.sync.aligned.m8n8.x4.trans.shared.b16 {%0,%1,%2,%3}, [%4];"
                 : "=r"(r[0]), "=r"(r[1]), "=r"(r[2]), "=r"(r[3]) : "r"(addr));
}
__device__ __forceinline__ void ldsm_x2_t(uint32_t* r, uint32_t addr) {
    asm volatile("ldmatrix.sync.aligned.m8n8.x2.trans.shared.b16 {%0,%1}, [%2];"
                 : "=r"(r[0]), "=r"(r[1]) : "r"(addr));
}

__device__ __forceinline__ void mma_f16(float* c, const uint32_t* a,
                                        uint32_t b0, uint32_t b1) {
    asm volatile(
        "mma.sync.aligned.m16n8k16.row.col.f32.f16.f16.f32 "
        "{%0,%1,%2,%3},{%4,%5,%6,%7},{%8,%9},{%0,%1,%2,%3};"
        : "+f"(c[0]), "+f"(c[1]), "+f"(c[2]), "+f"(c[3])
        : "r"(a[0]), "r"(a[1]), "r"(a[2]), "r"(a[3]), "r"(b0), "r"(b1));
}

// ---- prepass: fp32 -> fp16, vectorized grid-stride ----
__global__ void __launch_bounds__(256)
cvt_kernel(const float4* __restrict__ src, uint2* __restrict__ dst, int n4) {
    int stride = gridDim.x * blockDim.x;
    for (int i = blockIdx.x * blockDim.x + threadIdx.x; i < n4; i += stride) {
        float4 f = src[i];
        uint2 u;
        u.x = h2u(__floats2half2_rn(f.x, f.y));
        u.y = h2u(__floats2half2_rn(f.z, f.w));
        dst[i] = u;
    }
}

__global__ __launch_bounds__(NTHREADS, 2)
void lora_moe_h2(const int* __restrict__ m_sizes, float* __restrict__ out) {
    extern __shared__ __align__(128) char smem[];
    const uint32_t sb = (uint32_t)__cvta_generic_to_shared(smem);

    const int tid  = threadIdx.x;
    const int lane = tid & 31;
    const int warp = tid >> 5;
    const int wm   = warp & 3;   // m quarter (32 rows)
    const int wn   = warp >> 2;  // n half (64 cols)

    int* msz = (int*)(smem + SM_MSZ);
    if (tid < NEXP) msz[tid] = m_sizes[tid];
    __syncthreads();

    // ---- tile scan (m-tile index = blockIdx.y so adjacent CTAs share x tile) ----
    int e = 0, row_start = 0, m_len = 0, found = 0;
    {
        const int mt = blockIdx.y;
        int acc_rows = 0, acc_tiles = 0;
        for (e = 0; e < NEXP; e++) {
            int m  = msz[e];
            int nt = (m + BM - 1) >> 7;
            if (mt < acc_tiles + nt) {
                int lt    = mt - acc_tiles;
                row_start = acc_rows + lt * BM;
                m_len     = min(BM, m - lt * BM);
                found     = 1;
                break;
            }
            acc_tiles += nt;
            acc_rows  += m;
        }
    }
    if (!found) return;

    const int n0 = blockIdx.x * BN;
    const __half* xg  = g_xh  + (size_t)row_start * IN_DIM;
    const __half* bg  = g_wbh + (size_t)e * IN_DIM * OUT_DIM + n0;
    const __half* ag  = g_wah + (size_t)e * IN_DIM * RRANK;
    const __half* wbg = g_wsh + (size_t)e * RRANK  * OUT_DIM + n0;

    float acc[2][8][4];
    float aacc[2][4];
    #pragma unroll
    for (int i = 0; i < 2; i++) {
        #pragma unroll
        for (int j = 0; j < 8; j++)
            #pragma unroll
            for (int q = 0; q < 4; q++) acc[i][j][q] = 0.f;
        #pragma unroll
        for (int q = 0; q < 4; q++) aacc[i][q] = 0.f;
    }

    // ---- async stage loader (all fp16 srcs) ----
    auto load_stage = [&](int kt) {
        const int st = kt & 1;
        const uint32_t A  = sb + (st ? SM_A1  : SM_A0);
        const uint32_t B  = sb + (st ? SM_B1  : SM_B0);
        const uint32_t WA = sb + (st ? SM_WA1 : SM_WA0);
        const int k0 = kt * BK;
        // A: 128 rows x 64 halves = 1024 x 16B
        #pragma unroll
        for (int j = 0; j < 4; j++) {
            int idx = tid + j * NTHREADS;
            int row = idx >> 3, kc = idx & 7;
            bool v = (row_start + row) < T_TOK;
            cp16(A + row * SA + kc * 16, xg + (size_t)row * IN_DIM + k0 + kc * 8, v);
        }
        // B: 64 rows x 128 halves = 1024 x 16B
        #pragma unroll
        for (int j = 0; j < 4; j++) {
            int idx = tid + j * NTHREADS;
            int k = idx >> 4, nq = idx & 15;
            cp16(B + k * SB + nq * 16, bg + (size_t)(k0 + k) * OUT_DIM + nq * 8, true);
        }
        // WA: 64 rows x 16 halves = 128 x 16B
        if (tid < 128) {
            int k = tid >> 1, rq = tid & 1;
            cp16(WA + k * SWA + rq * 16, ag + (size_t)(k0 + k) * RRANK + rq * 8, true);
        }
        asm volatile("cp.async.commit_group;\n");
    };

    // per-lane ldmatrix base offsets
    const uint32_t a_off  = (uint32_t)((wm * 32 + (lane & 15)) * SA + (lane >> 4) * 16);
    const uint32_t b_off  = (uint32_t)((lane & 15) * SB + (wn * 64 + (lane >> 4) * 8) * 2);
    const uint32_t wa_off = (uint32_t)((lane & 15) * SWA + wn * 16);

    auto compute = [&](int st) {
        const uint32_t Ab = sb + (st ? SM_A1  : SM_A0) + a_off;
        const uint32_t Bb = sb + (st ? SM_B1  : SM_B0) + b_off;
        const uint32_t Wb = sb + (st ? SM_WA1 : SM_WA0) + wa_off;
        #pragma unroll
        for (int ks = 0; ks < 4; ks++) {   // 4 x K=16
            uint32_t am[2][4];
            ldsm_x4(am[0], Ab + ks * 32);
            ldsm_x4(am[1], Ab + ks * 32 + 16 * SA);
            uint32_t wf[2];
            ldsm_x2_t(wf, Wb + ks * 16 * SWA);
            #pragma unroll
            for (int p = 0; p < 4; p++) {
                uint32_t bf[4];
                ldsm_x4_t(bf, Bb + ks * 16 * SB + p * 32);
                mma_f16(acc[0][2 * p],     am[0], bf[0], bf[1]);
                mma_f16(acc[1][2 * p],     am[1], bf[0], bf[1]);
                mma_f16(acc[0][2 * p + 1], am[0], bf[2], bf[3]);
                mma_f16(acc[1][2 * p + 1], am[1], bf[2], bf[3]);
            }
            mma_f16(aacc[0], am[0], wf[0], wf[1]);
            mma_f16(aacc[1], am[1], wf[0], wf[1]);
        }
    };

    // ---- pipeline ----
    load_stage(0);
    #pragma unroll 1
    for (int kt = 0; kt < KT2; kt++) {
        if (kt + 1 < KT2) {
            load_stage(kt + 1);
            asm volatile("cp.async.wait_group 1;\n");
        } else {
            asm volatile("cp.async.wait_group 0;\n");
        }
        __syncthreads();
        compute(kt & 1);
        __syncthreads();
    }

    // ---- LoRA epilogue: a*SCALING -> A0 (fp16), w_b -> B0, K=16 mma ----
    {
        char* Asc = smem + SM_A0;
        const int row0 = wm * 32 + (lane >> 2);
        const int cb   = wn * 8 + 2 * (lane & 3);
        #pragma unroll
        for (int mf = 0; mf < 2; mf++) {
            int r = row0 + mf * 16;
            *(uint32_t*)(Asc + r * SA + cb * 2) =
                h2u(__floats2half2_rn(aacc[mf][0] * SCALING, aacc[mf][1] * SCALING));
            *(uint32_t*)(Asc + (r + 8) * SA + cb * 2) =
                h2u(__floats2half2_rn(aacc[mf][2] * SCALING, aacc[mf][3] * SCALING));
        }
    }
    {
        // w_b fp16: 16 rows x 128 halves = 256 x 16B
        char* Wbs = smem + SM_B0;
        int k = tid >> 4, nq = tid & 15;
        uint4 v = *(const uint4*)(wbg + (size_t)k * OUT_DIM + nq * 8);
        *(uint4*)(Wbs + k * SB + nq * 16) = v;
    }
    __syncthreads();

    {
        const int row = wm * 32 + (lane >> 2);
        uint32_t am[2][4];
        #pragma unroll
        for (int mf = 0; mf < 2; mf++) {
            const uint32_t base = sb + SM_A0 + (row + mf * 16) * SA + (lane & 3) * 4;
            asm volatile("ld.shared.b32 %0, [%1];" : "=r"(am[mf][0]) : "r"(base));
            asm volatile("ld.shared.b32 %0, [%1];" : "=r"(am[mf][1]) : "r"(base + 8 * SA));
            asm volatile("ld.shared.b32 %0, [%1];" : "=r"(am[mf][2]) : "r"(base + 16));
            asm volatile("ld.shared.b32 %0, [%1];" : "=r"(am[mf][3]) : "r"(base + 8 * SA + 16));
        }
        const uint32_t Bb = sb + SM_B0 + b_off;
        #pragma unroll
        for (int p = 0; p < 4; p++) {
            uint32_t bf[4];
            ldsm_x4_t(bf, Bb + p * 32);
            mma_f16(acc[0][2 * p],     am[0], bf[0], bf[1]);
            mma_f16(acc[1][2 * p],     am[1], bf[0], bf[1]);
            mma_f16(acc[0][2 * p + 1], am[0], bf[2], bf[3]);
            mma_f16(acc[1][2 * p + 1], am[1], bf[2], bf[3]);
        }
    }

    // ---- store ----
    {
        float* og = out + (size_t)row_start * OUT_DIM + n0;
        const int r0s = wm * 32 + (lane >> 2);
        const int c0s = wn * 64 + 2 * (lane & 3);
        #pragma unroll
        for (int mf = 0; mf < 2; mf++) {
            const int r1 = r0s + mf * 16;
            #pragma unroll
            for (int nf = 0; nf < 8; nf++) {
                const int cc = c0s + nf * 8;
                if (r1 < m_len)
                    *reinterpret_cast<float2*>(og + (size_t)r1 * OUT_DIM + cc) =
                        make_float2(acc[mf][nf][0], acc[mf][nf][1]);
                if (r1 + 8 < m_len)
                    *reinterpret_cast<float2*>(og + (size_t)(r1 + 8) * OUT_DIM + cc) =
                        make_float2(acc[mf][nf][2], acc[mf][nf][3]);
            }
        }
    }
}

extern "C" void kernel_launch(void* const* d_in, const int* in_sizes, int n_in,
                              void* d_out, int out_size) {
    const float* x      = (const float*)d_in[0];
    const int*   msz    = (const int*)  d_in[1];
    const float* w_base = (const float*)d_in[2];
    const float* w_a    = (const float*)d_in[3];
    const float* w_b    = (const float*)d_in[4];
    float*       out    = (float*)d_out;

    // resolve scratch symbol addresses (no allocation)
    static __half* p_xh = nullptr;
    static __half *p_wbh, *p_wah, *p_wsh;
    if (!p_xh) {
        cudaGetSymbolAddress((void**)&p_xh,  g_xh);
        cudaGetSymbolAddress((void**)&p_wbh, g_wbh);
        cudaGetSymbolAddress((void**)&p_wah, g_wah);
        cudaGetSymbolAddress((void**)&p_wsh, g_wsh);
    }

    // prepass conversions (in-stream ordering guarantees completion before GEMM)
    const int nx  = (int)((size_t)T_TOK * IN_DIM / 4);
    const int nwb = (int)((size_t)NEXP * IN_DIM * OUT_DIM / 4);
    const int nwa = (int)((size_t)NEXP * IN_DIM * RRANK / 4);
    const int nws = (int)((size_t)NEXP * RRANK * OUT_DIM / 4);
    cvt_kernel<<<8192, 256>>>((const float4*)x,      (uint2*)p_xh,  nx);
    cvt_kernel<<<8192, 256>>>((const float4*)w_base, (uint2*)p_wbh, nwb);
    cvt_kernel<<<2048, 256>>>((const float4*)w_a,    (uint2*)p_wah, nwa);
    cvt_kernel<<<512,  256>>>((const float4*)w_b,    (uint2*)p_wsh, nws);

    static int cfg_done = 0;
    if (!cfg_done) {
        cudaFuncSetAttribute(lora_moe_h2,
                             cudaFuncAttributeMaxDynamicSharedMemorySize, SMEM_BYTES);
        cfg_done = 1;
    }
    dim3 grid(NT, MAX_MTILES);   // n-tile fastest: adjacent CTAs share the x tile in L2
    lora_moe_h2<<<grid, NTHREADS, SMEM_BYTES>>>(msz, out);
}

// round 6
// speedup vs baseline: 1.0479x; 1.0479x over previous
#include <cuda_runtime.h>
#include <cuda_fp16.h>
#include <cstdint>

#define T_TOK   32768
#define IN_DIM  2048
#define OUT_DIM 768
#define NEXP    64
#define RRANK   16
#define SCALING 2.0f

#define BM 128
#define BN 128
#define BK 32
#define KT3 (IN_DIM / BK)                  /* 64 stages */
#define MAX_MTILES 320
#define NT 6
#define NTHREADS 128                       /* 4 warps, 2m x 2n, warp tile 64x64 */

// smem row strides (bytes), conflict-free for ldmatrix (stride/16 odd)
#define SA  80    /* A: 32 halves + pad;  5r mod 8 distinct  */
#define SB  272   /* B: 128 halves + pad; 17k mod 8 distinct */
#define SWA 48    /* WA: 16 halves + pad; 3k mod 8 distinct  */

#define A_STG  (128 * SA)   /* 10240 */
#define B_STG  (32 * SB)    /* 8704  */
#define WA_STG (32 * SWA)   /* 1536  */

#define SM_A   0
#define SM_B   (4 * A_STG)                 /* 40960 */
#define SM_WA  (SM_B + 4 * B_STG)          /* 75776 */
#define SM_MSZ (SM_WA + 4 * WA_STG)        /* 81920 */
#define SMEM_BYTES (SM_MSZ + 256)          /* 82176; 2 CTAs/SM */

// fp16 scratch (converted once per launch by prepass kernels)
__device__ __align__(16) __half g_xh [(size_t)T_TOK * IN_DIM];
__device__ __align__(16) __half g_wbh[(size_t)NEXP * IN_DIM * OUT_DIM];
__device__ __align__(16) __half g_wah[(size_t)NEXP * IN_DIM * RRANK];
__device__ __align__(16) __half g_wsh[(size_t)NEXP * RRANK * OUT_DIM];

__device__ __forceinline__ uint32_t h2u(__half2 h) {
    return *reinterpret_cast<uint32_t*>(&h);
}

__device__ __forceinline__ void cp16(uint32_t dst, const void* src, bool valid) {
    int sz = valid ? 16 : 0;   // sz=0 zero-fills, reads nothing
    asm volatile("cp.async.cg.shared.global [%0], [%1], 16, %2;\n"
                 :: "r"(dst), "l"(src), "r"(sz));
}

__device__ __forceinline__ void ldsm_x4(uint32_t* r, uint32_t addr) {
    asm volatile("ldmatrix.sync.aligned.m8n8.x4.shared.b16 {%0,%1,%2,%3}, [%4];"
                 : "=r"(r[0]), "=r"(r[1]), "=r"(r[2]), "=r"(r[3]) : "r"(addr));
}
__device__ __forceinline__ void ldsm_x4_t(uint32_t* r, uint32_t addr) {
    asm volatile("ldmatrix.sync.aligned.m8n8.x4.trans.shared.b16 {%0,%1,%2,%3}, [%4];"
                 : "=r"(r[0]), "=r"(r[1]), "=r"(r[2]), "=r"(r[3]) : "r"(addr));
}
__device__ __forceinline__ void ldsm_x2_t(uint32_t* r, uint32_t addr) {
    asm volatile("ldmatrix.sync.aligned.m8n8.x2.trans.shared.b16 {%0,%1}, [%2];"
                 : "=r"(r[0]), "=r"(r[1]) : "r"(addr));
}

__device__ __forceinline__ void mma_f16(float* c, const uint32_t* a,
                                        uint32_t b0, uint32_t b1) {
    asm volatile(
        "mma.sync.aligned.m16n8k16.row.col.f32.f16.f16.f32 "
        "{%0,%1,%2,%3},{%4,%5,%6,%7},{%8,%9},{%0,%1,%2,%3};"
        : "+f"(c[0]), "+f"(c[1]), "+f"(c[2]), "+f"(c[3])
        : "r"(a[0]), "r"(a[1]), "r"(a[2]), "r"(a[3]), "r"(b0), "r"(b1));
}

// ---- prepass: fp32 -> fp16, vectorized grid-stride ----
__global__ void __launch_bounds__(256)
cvt_kernel(const float4* __restrict__ src, uint2* __restrict__ dst, int n4) {
    int stride = gridDim.x * blockDim.x;
    for (int i = blockIdx.x * blockDim.x + threadIdx.x; i < n4; i += stride) {
        float4 f = src[i];
        uint2 u;
        u.x = h2u(__floats2half2_rn(f.x, f.y));
        u.y = h2u(__floats2half2_rn(f.z, f.w));
        dst[i] = u;
    }
}

__global__ __launch_bounds__(NTHREADS, 2)
void lora_moe_h3(const int* __restrict__ m_sizes, float* __restrict__ out) {
    extern __shared__ __align__(128) char smem[];
    const uint32_t sb = (uint32_t)__cvta_generic_to_shared(smem);

    const int tid  = threadIdx.x;
    const int lane = tid & 31;
    const int warp = tid >> 5;
    const int wm   = warp & 1;   // m half (64 rows)
    const int wn   = warp >> 1;  // n half (64 cols)

    int* msz = (int*)(smem + SM_MSZ);
    if (tid < NEXP) msz[tid] = m_sizes[tid];
    __syncthreads();

    // ---- tile scan (m-tile = blockIdx.y) ----
    int e = 0, row_start = 0, m_len = 0, found = 0;
    {
        const int mt = blockIdx.y;
        int acc_rows = 0, acc_tiles = 0;
        for (e = 0; e < NEXP; e++) {
            int m  = msz[e];
            int nt = (m + BM - 1) >> 7;
            if (mt < acc_tiles + nt) {
                int lt    = mt - acc_tiles;
                row_start = acc_rows + lt * BM;
                m_len     = min(BM, m - lt * BM);
                found     = 1;
                break;
            }
            acc_tiles += nt;
            acc_rows  += m;
        }
    }
    if (!found) return;

    const int n0 = blockIdx.x * BN;
    const __half* xg  = g_xh  + (size_t)row_start * IN_DIM;
    const __half* bg  = g_wbh + (size_t)e * IN_DIM * OUT_DIM + n0;
    const __half* ag  = g_wah + (size_t)e * IN_DIM * RRANK;
    const __half* wbg = g_wsh + (size_t)e * RRANK  * OUT_DIM + n0;

    float acc[4][8][4];    // 4 m-frags x 8 n-frags
    float aacc[4][4];      // 4 m-frags x 1 n-frag (rank split by wn)
    #pragma unroll
    for (int i = 0; i < 4; i++) {
        #pragma unroll
        for (int j = 0; j < 8; j++)
            #pragma unroll
            for (int q = 0; q < 4; q++) acc[i][j][q] = 0.f;
        #pragma unroll
        for (int q = 0; q < 4; q++) aacc[i][q] = 0.f;
    }

    // ---- async stage loader ----
    auto load_stage = [&](int kt) {
        const int st = kt & 3;
        const uint32_t A  = sb + SM_A  + st * A_STG;
        const uint32_t B  = sb + SM_B  + st * B_STG;
        const uint32_t WA = sb + SM_WA + st * WA_STG;
        const int k0 = kt * BK;
        // A: 128 rows x 32 halves = 512 x 16B
        #pragma unroll
        for (int j = 0; j < 4; j++) {
            int idx = tid + j * NTHREADS;
            int row = idx >> 2, kc = idx & 3;
            bool v = (row_start + row) < T_TOK;
            cp16(A + row * SA + kc * 16, xg + (size_t)row * IN_DIM + k0 + kc * 8, v);
        }
        // B: 32 rows x 128 halves = 512 x 16B
        #pragma unroll
        for (int j = 0; j < 4; j++) {
            int idx = tid + j * NTHREADS;
            int k = idx >> 4, nq = idx & 15;
            cp16(B + k * SB + nq * 16, bg + (size_t)(k0 + k) * OUT_DIM + nq * 8, true);
        }
        // WA: 32 rows x 16 halves = 64 x 16B
        if (tid < 64) {
            int k = tid >> 1, rq = tid & 1;
            cp16(WA + k * SWA + rq * 16, ag + (size_t)(k0 + k) * RRANK + rq * 8, true);
        }
        asm volatile("cp.async.commit_group;\n");
    };

    // per-lane ldmatrix base offsets
    const uint32_t a_off  = (uint32_t)((wm * 64 + (lane & 15)) * SA + (lane >> 4) * 16);
    const uint32_t b_off  = (uint32_t)((lane & 15) * SB + (wn * 64 + (lane >> 4) * 8) * 2);
    const uint32_t wa_off = (uint32_t)((lane & 15) * SWA + wn * 16);

    auto compute = [&](int st) {
        const uint32_t Ab = sb + SM_A  + st * A_STG  + a_off;
        const uint32_t Bb = sb + SM_B  + st * B_STG  + b_off;
        const uint32_t Wb = sb + SM_WA + st * WA_STG + wa_off;
        #pragma unroll
        for (int ks = 0; ks < 2; ks++) {   // 2 x K=16
            uint32_t am[4][4];
            #pragma unroll
            for (int mf = 0; mf < 4; mf++)
                ldsm_x4(am[mf], Ab + mf * 16 * SA + ks * 32);
            uint32_t wf[2];
            ldsm_x2_t(wf, Wb + ks * 16 * SWA);
            #pragma unroll
            for (int p = 0; p < 4; p++) {
                uint32_t bf[4];
                ldsm_x4_t(bf, Bb + ks * 16 * SB + p * 32);
                #pragma unroll
                for (int mf = 0; mf < 4; mf++) {
                    mma_f16(acc[mf][2 * p],     am[mf], bf[0], bf[1]);
                    mma_f16(acc[mf][2 * p + 1], am[mf], bf[2], bf[3]);
                }
            }
            #pragma unroll
            for (int mf = 0; mf < 4; mf++)
                mma_f16(aacc[mf], am[mf], wf[0], wf[1]);
        }
    };

    // ---- 4-stage pipeline, one barrier per stage ----
    load_stage(0);
    load_stage(1);
    load_stage(2);
    #pragma unroll 1
    for (int kt = 0; kt < KT3; kt++) {
        if (kt < KT3 - 2)      asm volatile("cp.async.wait_group 2;\n");
        else if (kt == KT3 - 2) asm volatile("cp.async.wait_group 1;\n");
        else                    asm volatile("cp.async.wait_group 0;\n");
        __syncthreads();
        if (kt + 3 < KT3) load_stage(kt + 3);
        compute(kt & 3);
    }
    __syncthreads();

    // ---- LoRA epilogue: a*SCALING -> A stage0 (fp16), w_b -> B stage0, K=16 mma ----
    {
        char* Asc = smem + SM_A;
        const int row0 = wm * 64 + (lane >> 2);
        const int cb   = wn * 8 + 2 * (lane & 3);
        #pragma unroll
        for (int mf = 0; mf < 4; mf++) {
            int r = row0 + mf * 16;
            *(uint32_t*)(Asc + r * SA + cb * 2) =
                h2u(__floats2half2_rn(aacc[mf][0] * SCALING, aacc[mf][1] * SCALING));
            *(uint32_t*)(Asc + (r + 8) * SA + cb * 2) =
                h2u(__floats2half2_rn(aacc[mf][2] * SCALING, aacc[mf][3] * SCALING));
        }
    }
    {
        // w_b fp16: 16 rows x 128 halves = 256 x 16B
        char* Wbs = smem + SM_B;
        #pragma unroll
        for (int j = 0; j < 2; j++) {
            int idx = tid + j * NTHREADS;
            int k = idx >> 4, nq = idx & 15;
            uint4 v = *(const uint4*)(wbg + (size_t)k * OUT_DIM + nq * 8);
            *(uint4*)(Wbs + k * SB + nq * 16) = v;
        }
    }
    __syncthreads();

    {
        const int row = wm * 64 + (lane >> 2);
        uint32_t am[4][4];
        #pragma unroll
        for (int mf = 0; mf < 4; mf++) {
            const uint32_t base = sb + SM_A + (row + mf * 16) * SA + (lane & 3) * 4;
            asm volatile("ld.shared.b32 %0, [%1];" : "=r"(am[mf][0]) : "r"(base));
            asm volatile("ld.shared.b32 %0, [%1];" : "=r"(am[mf][1]) : "r"(base + 8 * SA));
            asm volatile("ld.shared.b32 %0, [%1];" : "=r"(am[mf][2]) : "r"(base + 16));
            asm volatile("ld.shared.b32 %0, [%1];" : "=r"(am[mf][3]) : "r"(base + 8 * SA + 16));
        }
        const uint32_t Bb = sb + SM_B + b_off;
        #pragma unroll
        for (int p = 0; p < 4; p++) {
            uint32_t bf[4];
            ldsm_x4_t(bf, Bb + p * 32);
            #pragma unroll
            for (int mf = 0; mf < 4; mf++) {
                mma_f16(acc[mf][2 * p],     am[mf], bf[0], bf[1]);
                mma_f16(acc[mf][2 * p + 1], am[mf], bf[2], bf[3]);
            }
        }
    }

    // ---- store ----
    {
        float* og = out + (size_t)row_start * OUT_DIM + n0;
        const int r0s = wm * 64 + (lane >> 2);
        const int c0s = wn * 64 + 2 * (lane & 3);
        #pragma unroll
        for (int mf = 0; mf < 4; mf++) {
            const int r1 = r0s + mf * 16;
            #pragma unroll
            for (int nf = 0; nf < 8; nf++) {
                const int cc = c0s + nf * 8;
                if (r1 < m_len)
                    *reinterpret_cast<float2*>(og + (size_t)r1 * OUT_DIM + cc) =
                        make_float2(acc[mf][nf][0], acc[mf][nf][1]);
                if (r1 + 8 < m_len)
                    *reinterpret_cast<float2*>(og + (size_t)(r1 + 8) * OUT_DIM + cc) =
                        make_float2(acc[mf][nf][2], acc[mf][nf][3]);
            }
        }
    }
}

extern "C" void kernel_launch(void* const* d_in, const int* in_sizes, int n_in,
                              void* d_out, int out_size) {
    const float* x      = (const float*)d_in[0];
    const int*   msz    = (const int*)  d_in[1];
    const float* w_base = (const float*)d_in[2];
    const float* w_a    = (const float*)d_in[3];
    const float* w_b    = (const float*)d_in[4];
    float*       out    = (float*)d_out;

    static __half* p_xh = nullptr;
    static __half *p_wbh, *p_wah, *p_wsh;
    if (!p_xh) {
        cudaGetSymbolAddress((void**)&p_xh,  g_xh);
        cudaGetSymbolAddress((void**)&p_wbh, g_wbh);
        cudaGetSymbolAddress((void**)&p_wah, g_wah);
        cudaGetSymbolAddress((void**)&p_wsh, g_wsh);
    }

    const int nx  = (int)((size_t)T_TOK * IN_DIM / 4);
    const int nwb = (int)((size_t)NEXP * IN_DIM * OUT_DIM / 4);
    const int nwa = (int)((size_t)NEXP * IN_DIM * RRANK / 4);
    const int nws = (int)((size_t)NEXP * RRANK * OUT_DIM / 4);
    cvt_kernel<<<8192, 256>>>((const float4*)x,      (uint2*)p_xh,  nx);
    cvt_kernel<<<8192, 256>>>((const float4*)w_base, (uint2*)p_wbh, nwb);
    cvt_kernel<<<2048, 256>>>((const float4*)w_a,    (uint2*)p_wah, nwa);
    cvt_kernel<<<512,  256>>>((const float4*)w_b,    (uint2*)p_wsh, nws);

    static int cfg_done = 0;
    if (!cfg_done) {
        cudaFuncSetAttribute(lora_moe_h3,
                             cudaFuncAttributeMaxDynamicSharedMemorySize, SMEM_BYTES);
        cfg_done = 1;
    }
    dim3 grid(NT, MAX_MTILES);
    lora_moe_h3<<<grid, NTHREADS, SMEM_BYTES>>>(msz, out);
}